// round 14
// baseline (speedup 1.0000x reference)
#include <cuda_runtime.h>
#include <cuda_fp16.h>
#include <math.h>
#include <stdint.h>

// ---------------- problem constants ----------------
#define B_    16
#define T_    12
#define N_    2048
#define D_    128
#define INNER_ 256
#define BT_   (B_*T_)          // 192
#define ROWS_ (B_*T_*N_)       // 393216
#define BN_   (B_*N_)          // 32768
#define NN_   ((size_t)N_*N_)
#define XLD_  640              // Xcat row stride (spatial concat)
#define XTLD_ 256              // Xt row stride (temporal)

// ---------------- scratch (device globals) ----------------
#define SZ_H  ((size_t)ROWS_*D_)
#define SZ_PR ((size_t)ROWS_*512)
#define SZ_DSO ((size_t)ROWS_*768)
#define SZ_X  ((size_t)ROWS_*XLD_)
#define SZ_XT ((size_t)ROWS_*XTLD_)
#define SZ_HT ((size_t)BT_*D_*N_)

__device__ __align__(16) float g_h2  [SZ_H];
__device__ __align__(16) float g_bcat[2*768];

__device__ __align__(16) __half g_sp [SZ_H];    // fp16 spatial branch output (post-gelu)
__device__ __align__(16) __half g_tp [SZ_H];    // fp16 temporal branch output
__device__ __align__(16) __half g_pr [SZ_PR];   // fp16: cols 0..255 signal, 256..511 gate
__device__ __align__(16) __half g_dso[SZ_DSO];  // fp16: delta | si | so
__device__ __align__(16) __half g_X  [SZ_X];    // spatial concat activations [M][640]
__device__ __align__(16) __half g_Xt [SZ_XT];   // temporal activations [bn*T+t][256]
__device__ __align__(16) __half g_St [2*NN_];   // S^T fp16 [i][m][k]
__device__ __align__(16) __half g_Sh [2*NN_];   // S  fp16 row-major [i][k][n]
__device__ __align__(16) __half g_St2[2*NN_];   // (S^2)^T fp16 [i][m][k]
__device__ __align__(16) __half g_Ht0[SZ_HT];   // Ht(h)

// transposed weights per layer (fp16); dl/si/so contiguous => fused N=768 GEMM
#define WOFF_GCN 0
#define WOFF_IN  81920
#define WOFF_DL  147456
#define WOFF_OUT 344064
#define WSZ_L    376832
__device__ __align__(16) __half g_Wt[2*WSZ_L];

// ---------------- helpers ----------------
__device__ __forceinline__ float sigmoidf_(float x) { return 1.f / (1.f + expf(-x)); }
__device__ __forceinline__ float softplusf_(float x) {
    return fmaxf(x, 0.f) + log1pf(expf(-fabsf(x)));
}
__device__ __forceinline__ float geluf_(float x) {
    return 0.5f * x * (1.f + erff(x * 0.7071067811865475f));
}
__device__ __forceinline__ uint32_t smem_u32_(const void* p) {
    uint32_t a;
    asm("{ .reg .u64 t; cvta.to.shared.u64 t, %1; cvt.u32.u64 %0, t; }" : "=r"(a) : "l"(p));
    return a;
}
__device__ __forceinline__ void ldsm4_(uint32_t* r, uint32_t a) {
    asm volatile("ldmatrix.sync.aligned.m8n8.x4.shared.b16 {%0,%1,%2,%3}, [%4];"
        : "=r"(r[0]), "=r"(r[1]), "=r"(r[2]), "=r"(r[3]) : "r"(a));
}
__device__ __forceinline__ void mma16816_(float* d, const uint32_t* a, uint32_t b0, uint32_t b1) {
    asm volatile(
        "mma.sync.aligned.m16n8k16.row.col.f32.f16.f16.f32 "
        "{%0,%1,%2,%3}, {%4,%5,%6,%7}, {%8,%9}, {%0,%1,%2,%3};"
        : "+f"(d[0]), "+f"(d[1]), "+f"(d[2]), "+f"(d[3])
        : "r"(a[0]), "r"(a[1]), "r"(a[2]), "r"(a[3]), "r"(b0), "r"(b1));
}
// swizzled tile address: tile rows x 64 k fp16 (128B/row, 8 granules of 16B)
__device__ __forceinline__ uint32_t swadr_(uint32_t base, int row, int g) {
    return base + (uint32_t)(row * 128 + ((g ^ (row & 7)) << 4));
}

// ---------------- conversions ----------------
__global__ void convt_S(const float* __restrict__ S, __half* __restrict__ out)
{
    __shared__ float t[32][33];
    const int k0 = blockIdx.x * 32, m0 = blockIdx.y * 32, i = blockIdx.z;
    const int tx = threadIdx.x & 31, ty = threadIdx.x >> 5;
    const float* Si = S + (size_t)i * NN_;
    for (int r = ty; r < 32; r += 8)
        t[r][tx] = Si[(size_t)(k0 + r) * N_ + m0 + tx];
    __syncthreads();
    for (int r = ty; r < 32; r += 8) {
        size_t o = (size_t)i * NN_ + (size_t)(m0 + r) * N_ + k0 + tx;
        out[o] = __float2half_rn(t[tx][r]);
    }
}
__global__ void conv_copy(const float* __restrict__ src, __half* __restrict__ dst)
{
    size_t e = ((size_t)blockIdx.x * blockDim.x + threadIdx.x) * 2;
    float2 v = *(const float2*)(src + e);
    *(__half2*)(dst + e) = __floats2half2_rn(v.x, v.y);
}
__global__ void convt_H(const float* __restrict__ H, __half* __restrict__ out)
{
    __shared__ float t[32][33];
    const int n0 = blockIdx.x * 32, d0 = blockIdx.y * 32, z = blockIdx.z;
    const int tx = threadIdx.x & 31, ty = threadIdx.x >> 5;
    const float* Hz = H + (size_t)z * N_ * D_;
    for (int r = ty; r < 32; r += 8)
        t[r][tx] = Hz[(size_t)(n0 + r) * D_ + d0 + tx];
    __syncthreads();
    for (int r = ty; r < 32; r += 8) {
        size_t o = ((size_t)z * D_ + d0 + r) * N_ + n0 + tx;
        out[o] = __float2half_rn(t[tx][r]);
    }
}
__global__ void convt_W(const float* __restrict__ W, int K, int N, __half* __restrict__ out)
{
    __shared__ float t[32][33];
    const int k0 = blockIdx.x * 32, n0 = blockIdx.y * 32;
    const int tx = threadIdx.x & 31, ty = threadIdx.x >> 5;
    for (int r = ty; r < 32; r += 8)
        t[r][tx] = W[(size_t)(k0 + r) * N + n0 + tx];
    __syncthreads();
    for (int r = ty; r < 32; r += 8) {
        size_t o = (size_t)(n0 + r) * K + k0 + tx;
        out[o] = __float2half_rn(t[tx][r]);
    }
}
__global__ void bias_cat(const float* __restrict__ d, const float* __restrict__ s,
                         const float* __restrict__ o, float* __restrict__ out)
{
    int l = blockIdx.x, t = threadIdx.x;
    const float* src = (t < 256) ? d : ((t < 512) ? s : o);
    out[l * 768 + t] = src[l * 256 + (t & 255)];
}
__global__ void conv_plain(const float* __restrict__ src, __half* __restrict__ x)
{
    size_t e = ((size_t)blockIdx.x * blockDim.x + threadIdx.x) * 2;
    size_t row = e >> 7;
    int col = (int)(e & 127);
    float2 v = *(const float2*)(src + e);
    *(__half2*)(x + row * XLD_ + col) = __floats2half2_rn(v.x, v.y);
}
__global__ void transpose_convert_bt(const float* __restrict__ h, __half* __restrict__ x)
{
    size_t gid = (size_t)blockIdx.x * blockDim.x + threadIdx.x;
    int q = (int)(gid & 31);
    int r = (int)(gid >> 5);
    int t = r % T_;
    int bn = r / T_;
    int n = bn % N_;
    int b = bn / N_;
    size_t src = ((size_t)((b * T_ + t) * N_) + n) * D_ + q * 4;
    float4 v = *(const float4*)(h + src);
    size_t o = (size_t)r * XTLD_ + q * 4;
    *(__half2*)(x + o)     = __floats2half2_rn(v.x, v.y);
    *(__half2*)(x + o + 2) = __floats2half2_rn(v.z, v.w);
}

// ---------------- HMMA GEMM infrastructure (k64, swizzled, 3-stage) ----------------
#define TILEB_ 16384                  // 128 rows x 128B
#define STAGEB_ (2 * TILEB_)          // 32768
#define NSTG_ 3
#define SMEM_MMA (NSTG_ * STAGEB_)    // 98304 (rows GEMM)

// einsum z2 tiles: A 128 rows, B 256 rows
#define STAGE4_ 49152                 // 16384 + 32768
#define SMEM_SUP (NSTG_ * STAGE4_)    // 147456

// ---------------- 4-way support einsum, two z per CTA (128m x 256n tile) -------
// blockIdx.x>>4 selects q; blockIdx.y selects z-pair. B rows 0..255 are the
// contiguous d-rows of z0 and z0+1 in Ht.
__global__ void __launch_bounds__(256)
gemm_support4(const __half* __restrict__ A0, const __half* __restrict__ A1,
              const __half* __restrict__ A2, const __half* __restrict__ A3,
              const __half* __restrict__ Bm, __half* __restrict__ Xb)
{
    extern __shared__ char smem[];
    const uint32_t sbase = smem_u32_(smem);
    const int q   = blockIdx.x >> 4;
    const int m0  = (blockIdx.x & 15) * 128;
    const int z0  = blockIdx.y * 2;
    const int tid = threadIdx.x;
    const int wid = tid >> 5, lid = tid & 31;
    const int wm = wid & 1, wn = wid >> 1;      // 2 x 4 warp grid (64m x 64n each)
    const int m_off = wm * 64, n_off = wn * 64;

    const __half* Aq = (q == 0) ? A0 : (q == 1) ? A1 : (q == 2) ? A2 : A3;
    __half* Xs = Xb + 128 * (q + 1);
    const __half* gA = Aq + (size_t)m0 * N_;
    const __half* gB = Bm + (size_t)z0 * D_ * N_;   // 256 contiguous rows

    auto load_stage = [&](int buf, int k0) {
        uint32_t base = sbase + buf * STAGE4_;
#pragma unroll
        for (int i = 0; i < 12; i++) {
            int idx = i * 256 + tid;              // 0..3071
            if (idx < 1024) {
                int r = idx >> 3, g = idx & 7;
                uint32_t dst = swadr_(base, r, g);
                const void* src = gA + (size_t)r * N_ + k0 + g * 8;
                asm volatile("cp.async.cg.shared.global [%0], [%1], 16;" :: "r"(dst), "l"(src));
            } else {
                int rem = idx - 1024;
                int r = rem >> 3, g = rem & 7;
                uint32_t dst = swadr_(base + 16384, r, g);
                const void* src = gB + (size_t)r * N_ + k0 + g * 8;
                asm volatile("cp.async.cg.shared.global [%0], [%1], 16;" :: "r"(dst), "l"(src));
            }
        }
        asm volatile("cp.async.commit_group;" ::: "memory");
    };

    float acc[4][8][4];
#pragma unroll
    for (int mt = 0; mt < 4; mt++)
#pragma unroll
        for (int nt = 0; nt < 8; nt++)
#pragma unroll
            for (int qq = 0; qq < 4; qq++) acc[mt][nt][qq] = 0.f;

    const int a_row = m_off + (lid & 15);
    const int a_g   = (lid >> 4);
    const int b_row = n_off + ((lid >> 4) << 3) + (lid & 7);
    const int b_g   = ((lid >> 3) & 1);

    const int NT = N_ / 64;                       // 32
    load_stage(0, 0);
    load_stage(1, 64);
    for (int kt = 0; kt < NT; kt++) {
        if (kt + 1 < NT) asm volatile("cp.async.wait_group 1;" ::: "memory");
        else             asm volatile("cp.async.wait_group 0;" ::: "memory");
        __syncthreads();
        if (kt + 2 < NT) load_stage((kt + 2) % NSTG_, (kt + 2) * 64);

        const uint32_t stg = sbase + (kt % NSTG_) * STAGE4_;
        const uint32_t bA = stg, bB = stg + 16384;
#pragma unroll
        for (int k16 = 0; k16 < 4; k16++) {
            const int gb = k16 * 2;
            uint32_t ah[4][4];
#pragma unroll
            for (int mt = 0; mt < 4; mt++)
                ldsm4_(ah[mt], swadr_(bA, a_row + mt * 16, gb + a_g));
#pragma unroll
            for (int pt = 0; pt < 4; pt++) {
                uint32_t bh[4];
                ldsm4_(bh, swadr_(bB, b_row + pt * 16, gb + b_g));
#pragma unroll
                for (int mt = 0; mt < 4; mt++) {
#pragma unroll
                    for (int sub = 0; sub < 2; sub++)
                        mma16816_(acc[mt][pt * 2 + sub], ah[mt], bh[2 * sub], bh[2 * sub + 1]);
                }
            }
        }
    }

    // epilogue: warp's 64 columns belong to a single z (n_off>>7) and d-base n_off&127
    const int zz  = z0 + (n_off >> 7);
    const int d0c = n_off & 127;
#pragma unroll
    for (int mt = 0; mt < 4; mt++) {
        const int r0 = m0 + m_off + mt * 16 + (lid >> 2);
        __half* x0 = Xs + ((size_t)zz * N_ + r0) * XLD_ + d0c;
        __half* x1 = Xs + ((size_t)zz * N_ + r0 + 8) * XLD_ + d0c;
#pragma unroll
        for (int nt = 0; nt < 8; nt++) {
            const int cc = nt * 8 + (lid & 3) * 2;
            *(__half2*)(x0 + cc) = __floats2half2_rn(acc[mt][nt][0], acc[mt][nt][1]);
            *(__half2*)(x1 + cc) = __floats2half2_rn(acc[mt][nt][2], acc[mt][nt][3]);
        }
    }
}

// ---------------- rows GEMM: C = act( X·Wt + bias ) ----------
template <int ACT, bool BIAS, bool HOUT>
__global__ void __launch_bounds__(256, 2)
gemm_rows_hmma(const __half* __restrict__ X, const __half* __restrict__ W,
               const float* __restrict__ bias, void* __restrict__ Cv,
               int K, int lda, int ldb, int ldc)
{
    extern __shared__ char smem[];
    const uint32_t sbase = smem_u32_(smem);
    const int j0  = blockIdx.x * 128;
    const int r0  = blockIdx.y * 128;
    const int tid = threadIdx.x;
    const int wid = tid >> 5, lid = tid & 31;
    const int wm = wid & 3, wn = wid >> 2;
    const int m_off = wm * 32, n_off = wn * 64;

    const __half* gp[2] = { X + (size_t)r0 * lda, W + (size_t)j0 * ldb };

    auto load_stage = [&](int buf, int k0) {
        uint32_t base = sbase + buf * STAGEB_;
#pragma unroll
        for (int i = 0; i < 8; i++) {
            int idx = i * 256 + tid;
            int tile = idx >> 10;
            int rem = idx & 1023;
            int r = rem >> 3, g = rem & 7;
            int ld = (tile == 0) ? lda : ldb;
            uint32_t dst = swadr_(base + tile * TILEB_, r, g);
            const void* src = gp[tile] + (size_t)r * ld + k0 + g * 8;
            asm volatile("cp.async.cg.shared.global [%0], [%1], 16;" :: "r"(dst), "l"(src));
        }
        asm volatile("cp.async.commit_group;" ::: "memory");
    };

    float acc[2][8][4];
#pragma unroll
    for (int mt = 0; mt < 2; mt++)
#pragma unroll
        for (int nt = 0; nt < 8; nt++)
#pragma unroll
            for (int q = 0; q < 4; q++) acc[mt][nt][q] = 0.f;

    const int a_row = m_off + (lid & 15);
    const int a_g   = (lid >> 4);
    const int b_row = n_off + ((lid >> 4) << 3) + (lid & 7);
    const int b_g   = ((lid >> 3) & 1);

    const int NT = K >> 6;
    load_stage(0, 0);
    load_stage(1, 64);
    for (int kt = 0; kt < NT; kt++) {
        if (kt + 1 < NT) asm volatile("cp.async.wait_group 1;" ::: "memory");
        else             asm volatile("cp.async.wait_group 0;" ::: "memory");
        __syncthreads();
        if (kt + 2 < NT) load_stage((kt + 2) % NSTG_, (kt + 2) * 64);

        const uint32_t stg = sbase + (kt % NSTG_) * STAGEB_;
        const uint32_t bA = stg, bB = stg + TILEB_;
#pragma unroll
        for (int k16 = 0; k16 < 4; k16++) {
            const int gb = k16 * 2;
            uint32_t ah[2][4];
#pragma unroll
            for (int mt = 0; mt < 2; mt++)
                ldsm4_(ah[mt], swadr_(bA, a_row + mt * 16, gb + a_g));
#pragma unroll
            for (int pt = 0; pt < 4; pt++) {
                uint32_t bh[4];
                ldsm4_(bh, swadr_(bB, b_row + pt * 16, gb + b_g));
#pragma unroll
                for (int mt = 0; mt < 2; mt++) {
#pragma unroll
                    for (int sub = 0; sub < 2; sub++)
                        mma16816_(acc[mt][pt * 2 + sub], ah[mt], bh[2 * sub], bh[2 * sub + 1]);
                }
            }
        }
    }

    auto ep = [&](float v, float b) -> float {
        if (BIAS) v += b;
        if (ACT == 1) v = softplusf_(v);
        else if (ACT == 2) v = tanhf(v);
        else if (ACT == 3) v = (j0 < 256) ? softplusf_(v) : tanhf(v);
        else if (ACT == 4) v = geluf_(v);
        return v;
    };
#pragma unroll
    for (int mt = 0; mt < 2; mt++) {
        const int r = r0 + m_off + mt * 16 + (lid >> 2);
#pragma unroll
        for (int nt = 0; nt < 8; nt++) {
            const int cc = n_off + nt * 8 + (lid & 3) * 2;
            float b0 = 0.f, b1 = 0.f;
            if (BIAS) { b0 = bias[j0 + cc]; b1 = bias[j0 + cc + 1]; }
            float v0 = ep(acc[mt][nt][0], b0), v1 = ep(acc[mt][nt][1], b1);
            float v2 = ep(acc[mt][nt][2], b0), v3 = ep(acc[mt][nt][3], b1);
            if (HOUT) {
                __half* c0 = (__half*)Cv + (size_t)r * ldc + j0 + cc;
                __half* c1 = (__half*)Cv + (size_t)(r + 8) * ldc + j0 + cc;
                *(__half2*)c0 = __floats2half2_rn(v0, v1);
                *(__half2*)c1 = __floats2half2_rn(v2, v3);
            } else {
                float* c0 = (float*)Cv + (size_t)r * ldc + j0 + cc;
                float* c1 = (float*)Cv + (size_t)(r + 8) * ldc + j0 + cc;
                *(float2*)c0 = make_float2(v0, v1);
                *(float2*)c1 = make_float2(v2, v3);
            }
        }
    }
}

// ---------------- causal depthwise conv (K=4) + SiLU; sig -> Xt cols 0..255 -----
__global__ void conv_silu_kernel(const __half* __restrict__ pr, const float* __restrict__ cw,
                                 const float* __restrict__ cb, __half* __restrict__ x)
{
    int idx = blockIdx.x * blockDim.x + threadIdx.x;
    int c = idx & (INNER_ - 1);
    int bn = idx >> 8;
    float w0 = cw[c * 4 + 0], w1 = cw[c * 4 + 1], w2 = cw[c * 4 + 2], w3 = cw[c * 4 + 3];
    float b = cb[c];
    float s[T_];
    size_t base = (size_t)bn * T_ * 512 + c;
#pragma unroll
    for (int t = 0; t < T_; t++) s[t] = __half2float(pr[base + (size_t)t * 512]);
    size_t ox = (size_t)bn * T_ * XTLD_ + c;
#pragma unroll
    for (int t = 0; t < T_; t++) {
        float a = b + w3 * s[t];
        if (t >= 1) a += w2 * s[t - 1];
        if (t >= 2) a += w1 * s[t - 2];
        if (t >= 3) a += w0 * s[t - 3];
        float v = a * sigmoidf_(a);
        x[ox + (size_t)t * XTLD_] = __float2half_rn(v);
    }
}

// ---------------- selective-scan + gating; reads Xt sig, overwrites with y ------
__global__ void scan_kernel(const __half* __restrict__ dso, const __half* __restrict__ pr,
                            const float* __restrict__ a_log, const float* __restrict__ d_skip,
                            __half* x)
{
    int idx = blockIdx.x * blockDim.x + threadIdx.x;
    int c = idx & (INNER_ - 1);
    int bn = idx >> 8;
    float a = -softplusf_(a_log[c]);
    float dsk = d_skip[c];
    float state = 0.f;
    size_t b768 = (size_t)bn * T_ * 768 + c;
    size_t b512 = (size_t)bn * T_ * 512 + c;
    size_t bx   = (size_t)bn * T_ * XTLD_ + c;
#pragma unroll
    for (int t = 0; t < T_; t++) {
        float xs = __half2float(x  [bx   + (size_t)t * XTLD_]);
        float d  = __half2float(dso[b768 + (size_t)t * 768]);
        float iv = __half2float(dso[b768 + (size_t)t * 768 + 256]);
        float ov = __half2float(dso[b768 + (size_t)t * 768 + 512]);
        float g  = __half2float(pr [b512 + (size_t)t * 512 + INNER_]);
        state = expf(d * a) * state + iv * xs;
        float yy = (ov * state + dsk * xs) * sigmoidf_(g);
        x[bx + (size_t)t * XTLD_] = __float2half_rn(yy);
    }
}

// ---------------- fusion + LayerNorm (sp gelu'd fp16, tp fp16); emits X h slice --
__global__ void fuse_ln_kernel(const float* __restrict__ h_in, const __half* __restrict__ sp,
                               const __half* __restrict__ tp,
                               const float* __restrict__ ln_g, const float* __restrict__ ln_b,
                               float* __restrict__ h_out, __half* __restrict__ xo)
{
    int token = blockIdx.x;
    int d = threadIdx.x;
    int n  = token % N_;
    int bt = token / N_;
    int t  = bt % T_;
    int b  = bt / T_;
    size_t row    = (size_t)token * D_;
    size_t row_tp = ((size_t)(b * N_ + n) * T_ + t) * D_;

    float hv = h_in[row + d];
    float s = __half2float(sp[row + d]);
    float tv = __half2float(tp[row_tp + d]);
    float f = hv + s + tv + s * tv;

    __shared__ float red[8];
    float v = f;
#pragma unroll
    for (int o = 16; o > 0; o >>= 1) v += __shfl_xor_sync(0xffffffffu, v, o);
    if ((d & 31) == 0) red[d >> 5] = v;
    __syncthreads();
    float mu = (red[0] + red[1] + red[2] + red[3]) * (1.f / 128.f);
    float dv = f - mu;
    v = dv * dv;
#pragma unroll
    for (int o = 16; o > 0; o >>= 1) v += __shfl_xor_sync(0xffffffffu, v, o);
    if ((d & 31) == 0) red[4 + (d >> 5)] = v;
    __syncthreads();
    float var = (red[4] + red[5] + red[6] + red[7]) * (1.f / 128.f);
    float out = dv * rsqrtf(var + 1e-5f) * ln_g[d] + ln_b[d];
    h_out[row + d] = out;
    xo[(size_t)token * XLD_ + d] = __float2half_rn(out);
}

// ---------------- host launcher ----------------
extern "C" void kernel_launch(void* const* d_in, const int* in_sizes, int n_in,
                              void* d_out, int out_size)
{
    (void)in_sizes; (void)n_in; (void)out_size;
    const float* inputs   = (const float*)d_in[0];
    const float* supports = (const float*)d_in[1];
    const float* gcn_w    = (const float*)d_in[2];
    const float* gcn_b    = (const float*)d_in[3];
    const float* in_w     = (const float*)d_in[4];
    const float* in_b     = (const float*)d_in[5];
    const float* conv_w   = (const float*)d_in[6];
    const float* conv_b   = (const float*)d_in[7];
    const float* delta_w  = (const float*)d_in[8];
    const float* delta_b  = (const float*)d_in[9];
    const float* si_w     = (const float*)d_in[10];
    const float* si_b     = (const float*)d_in[11];
    const float* so_w     = (const float*)d_in[12];
    const float* so_b     = (const float*)d_in[13];
    const float* a_log    = (const float*)d_in[14];
    const float* d_skip   = (const float*)d_in[15];
    const float* out_w    = (const float*)d_in[16];
    const float* out_b    = (const float*)d_in[17];
    const float* ln_g     = (const float*)d_in[18];
    const float* ln_b     = (const float*)d_in[19];

    float *h2, *bcat;
    __half *sp, *tp, *St, *Sh, *St2, *X, *Xt, *Wt, *Ht0, *pr, *dso;
    cudaGetSymbolAddress((void**)&h2,   g_h2);
    cudaGetSymbolAddress((void**)&bcat, g_bcat);
    cudaGetSymbolAddress((void**)&sp,   g_sp);
    cudaGetSymbolAddress((void**)&tp,   g_tp);
    cudaGetSymbolAddress((void**)&St,   g_St);
    cudaGetSymbolAddress((void**)&Sh,   g_Sh);
    cudaGetSymbolAddress((void**)&St2,  g_St2);
    cudaGetSymbolAddress((void**)&X,    g_X);
    cudaGetSymbolAddress((void**)&Xt,   g_Xt);
    cudaGetSymbolAddress((void**)&Wt,   g_Wt);
    cudaGetSymbolAddress((void**)&Ht0,  g_Ht0);
    cudaGetSymbolAddress((void**)&pr,   g_pr);
    cudaGetSymbolAddress((void**)&dso,  g_dso);

    static cudaStream_t s1 = nullptr;
    static cudaEvent_t evF[2], evJ[2];
    if (s1 == nullptr) {
        cudaStreamCreateWithFlags(&s1, cudaStreamNonBlocking);
        for (int i = 0; i < 2; i++) {
            cudaEventCreateWithFlags(&evF[i], cudaEventDisableTiming);
            cudaEventCreateWithFlags(&evJ[i], cudaEventDisableTiming);
        }
    }

    cudaFuncSetAttribute(gemm_support4, cudaFuncAttributeMaxDynamicSharedMemorySize, SMEM_SUP);
    cudaFuncSetAttribute(gemm_rows_hmma<0,true ,true >, cudaFuncAttributeMaxDynamicSharedMemorySize, SMEM_MMA);
    cudaFuncSetAttribute(gemm_rows_hmma<0,false,true >, cudaFuncAttributeMaxDynamicSharedMemorySize, SMEM_MMA);
    cudaFuncSetAttribute(gemm_rows_hmma<3,true ,true >, cudaFuncAttributeMaxDynamicSharedMemorySize, SMEM_MMA);
    cudaFuncSetAttribute(gemm_rows_hmma<4,true ,true >, cudaFuncAttributeMaxDynamicSharedMemorySize, SMEM_MMA);

    const dim3 blk(256);
    const dim3 gmma4(64, BT_ / 2);         // z-pairs
    const dim3 gcvH(64, 4, BT_);
    const dim3 gr1(1, ROWS_ / 128);
    const dim3 gr4(4, ROWS_ / 128);
    const dim3 gr6(6, ROWS_ / 128);
    const int ew_blocks = (BN_ * INNER_) / 256;

    // ---- prologue phase 1: temporal prerequisites, then fork layer-0 temporal ----
    for (int l = 0; l < 2; l++) {
        __half* w = Wt + (size_t)l * WSZ_L;
        convt_W<<<dim3(4, 16), blk>>>(in_w   + (size_t)l * 128 * 512, 128, 512, w + WOFF_IN);
        convt_W<<<dim3(8, 8),  blk>>>(delta_w + (size_t)l * 256 * 256, 256, 256, w + WOFF_DL);
        convt_W<<<dim3(8, 8),  blk>>>(si_w    + (size_t)l * 256 * 256, 256, 256, w + WOFF_DL + 65536);
        convt_W<<<dim3(8, 8),  blk>>>(so_w    + (size_t)l * 256 * 256, 256, 256, w + WOFF_DL + 131072);
        convt_W<<<dim3(8, 4),  blk>>>(out_w   + (size_t)l * 256 * 128, 256, 128, w + WOFF_OUT);
    }
    bias_cat<<<2, 768>>>(delta_b, si_b, so_b, bcat);
    cudaEventRecord(evF[0], 0);

    // ---- prologue phase 2: spatial setup (overlaps layer-0 temporal) ----
    for (int l = 0; l < 2; l++)
        convt_W<<<dim3(20, 4), blk>>>(gcn_w + (size_t)l * 640 * 128, 640, 128,
                                      Wt + (size_t)l * WSZ_L + WOFF_GCN);
    convt_S<<<dim3(64, 64, 2), blk>>>(supports, St);
    conv_copy<<<(int)(2 * NN_ / 512), blk>>>(supports, Sh);
    conv_plain<<<(int)(SZ_H / 512), blk>>>(inputs, X);
    gemm_rows_hmma<0,false,true><<<dim3(16, 16), blk, SMEM_MMA>>>(St,       Sh,       nullptr, St2,       2048, 2048, 2048, 2048);
    gemm_rows_hmma<0,false,true><<<dim3(16, 16), blk, SMEM_MMA>>>(St + NN_, Sh + NN_, nullptr, St2 + NN_, 2048, 2048, 2048, 2048);

    for (int l = 0; l < 2; l++) {
        const float* h_in  = (l == 0) ? inputs : h2;
        float*       h_out = (l == 0) ? h2 : (float*)d_out;
        const __half* w = Wt + (size_t)l * WSZ_L;
        const float* gb  = gcn_b  + l * 128;
        const float* ib  = in_b   + l * 512;
        const float* cw  = conv_w + (size_t)l * INNER_ * 4;
        const float* cb  = conv_b + l * INNER_;
        const float* al  = a_log  + l * INNER_;
        const float* dsk = d_skip + l * INNER_;
        const float* ob  = out_b + l * 128;
        const float* lg  = ln_g + l * 128;
        const float* lb  = ln_b + l * 128;

        // ---- fork: temporal branch on s1 ----
        if (l > 0) cudaEventRecord(evF[l], 0);
        cudaStreamWaitEvent(s1, evF[l], 0);
        transpose_convert_bt<<<(ROWS_ * 32) / 256, 256, 0, s1>>>(h_in, Xt);
        gemm_rows_hmma<0,true,true ><<<gr4, blk, SMEM_MMA, s1>>>(Xt, w + WOFF_IN, ib, pr, 128, XTLD_, 128, 512);
        conv_silu_kernel<<<ew_blocks, 256, 0, s1>>>(pr, cw, cb, Xt);
        gemm_rows_hmma<3,true,true ><<<gr6, blk, SMEM_MMA, s1>>>(Xt, w + WOFF_DL, bcat + l * 768, dso, 256, XTLD_, 256, 768);
        scan_kernel<<<ew_blocks, 256, 0, s1>>>(dso, pr, al, dsk, Xt);
        gemm_rows_hmma<0,true,true ><<<gr1, blk, SMEM_MMA, s1>>>(Xt, w + WOFF_OUT, ob, tp, 256, XTLD_, 256, 128);
        cudaEventRecord(evJ[l], s1);

        // ---- spatial branch: convt_H -> 4-way z2 einsum -> gcn GEMM (bias+gelu) ----
        convt_H<<<gcvH, blk>>>(h_in, Ht0);
        gemm_support4<<<gmma4, blk, SMEM_SUP>>>(St, St2, St + NN_, St2 + NN_, Ht0, X);
        gemm_rows_hmma<4,true,true><<<gr1, blk, SMEM_MMA>>>(X, w + WOFF_GCN, gb, sp, 640, XLD_, 640, 128);

        // ---- join + fusion/layernorm ----
        cudaStreamWaitEvent(0, evJ[l], 0);
        fuse_ln_kernel<<<ROWS_, 128>>>(h_in, sp, tp, lg, lb, h_out, X);
    }
}

// round 15
// speedup vs baseline: 1.0460x; 1.0460x over previous
#include <cuda_runtime.h>
#include <cuda_fp16.h>
#include <math.h>
#include <stdint.h>

// ---------------- problem constants ----------------
#define B_    16
#define T_    12
#define N_    2048
#define D_    128
#define INNER_ 256
#define BT_   (B_*T_)          // 192
#define ROWS_ (B_*T_*N_)       // 393216
#define BN_   (B_*N_)          // 32768
#define NN_   ((size_t)N_*N_)
#define XLD_  640              // Xcat row stride (spatial concat)
#define XTLD_ 256              // Xt row stride (temporal)

// ---------------- scratch (device globals) ----------------
#define SZ_H  ((size_t)ROWS_*D_)
#define SZ_PR ((size_t)ROWS_*512)
#define SZ_DSO ((size_t)ROWS_*768)
#define SZ_X  ((size_t)ROWS_*XLD_)
#define SZ_XT ((size_t)ROWS_*XTLD_)
#define SZ_HT ((size_t)BT_*D_*N_)

__device__ __align__(16) float g_h2  [SZ_H];
__device__ __align__(16) float g_bcat[2*768];

__device__ __align__(16) __half g_sp [SZ_H];    // fp16 spatial branch output (post-gelu)
__device__ __align__(16) __half g_tp [SZ_H];    // fp16 temporal branch output
__device__ __align__(16) __half g_pr [SZ_PR];   // fp16: cols 0..255 signal, 256..511 gate
__device__ __align__(16) __half g_dso[SZ_DSO];  // fp16: delta | si | so
__device__ __align__(16) __half g_X  [SZ_X];    // spatial concat activations [M][640]
__device__ __align__(16) __half g_Xt [SZ_XT];   // temporal activations [bn*T+t][256]
__device__ __align__(16) __half g_St [2*NN_];   // S^T fp16 [i][m][k]
__device__ __align__(16) __half g_Sh [2*NN_];   // S  fp16 row-major [i][k][n]
__device__ __align__(16) __half g_St2[2*NN_];   // (S^2)^T fp16 [i][m][k]
__device__ __align__(16) __half g_Ht0[SZ_HT];   // Ht(h)

// transposed weights per layer (fp16); dl/si/so contiguous => fused N=768 GEMM
#define WOFF_GCN 0
#define WOFF_IN  81920
#define WOFF_DL  147456
#define WOFF_OUT 344064
#define WSZ_L    376832
__device__ __align__(16) __half g_Wt[2*WSZ_L];

// ---------------- helpers ----------------
__device__ __forceinline__ float sigmoidf_(float x) { return 1.f / (1.f + expf(-x)); }
__device__ __forceinline__ float softplusf_(float x) {
    return fmaxf(x, 0.f) + log1pf(expf(-fabsf(x)));
}
__device__ __forceinline__ float geluf_(float x) {
    return 0.5f * x * (1.f + erff(x * 0.7071067811865475f));
}
__device__ __forceinline__ uint32_t smem_u32_(const void* p) {
    uint32_t a;
    asm("{ .reg .u64 t; cvta.to.shared.u64 t, %1; cvt.u32.u64 %0, t; }" : "=r"(a) : "l"(p));
    return a;
}
__device__ __forceinline__ void ldsm4_(uint32_t* r, uint32_t a) {
    asm volatile("ldmatrix.sync.aligned.m8n8.x4.shared.b16 {%0,%1,%2,%3}, [%4];"
        : "=r"(r[0]), "=r"(r[1]), "=r"(r[2]), "=r"(r[3]) : "r"(a));
}
__device__ __forceinline__ void mma16816_(float* d, const uint32_t* a, uint32_t b0, uint32_t b1) {
    asm volatile(
        "mma.sync.aligned.m16n8k16.row.col.f32.f16.f16.f32 "
        "{%0,%1,%2,%3}, {%4,%5,%6,%7}, {%8,%9}, {%0,%1,%2,%3};"
        : "+f"(d[0]), "+f"(d[1]), "+f"(d[2]), "+f"(d[3])
        : "r"(a[0]), "r"(a[1]), "r"(a[2]), "r"(a[3]), "r"(b0), "r"(b1));
}
// swizzled tile address: tile is 128 rows x 64 k fp16 (128B/row, 8 granules of 16B)
__device__ __forceinline__ uint32_t swadr_(uint32_t base, int row, int g) {
    return base + (uint32_t)(row * 128 + ((g ^ (row & 7)) << 4));
}

// ---------------- conversions ----------------
__global__ void convt_S(const float* __restrict__ S, __half* __restrict__ out)
{
    __shared__ float t[32][33];
    const int k0 = blockIdx.x * 32, m0 = blockIdx.y * 32, i = blockIdx.z;
    const int tx = threadIdx.x & 31, ty = threadIdx.x >> 5;
    const float* Si = S + (size_t)i * NN_;
    for (int r = ty; r < 32; r += 8)
        t[r][tx] = Si[(size_t)(k0 + r) * N_ + m0 + tx];
    __syncthreads();
    for (int r = ty; r < 32; r += 8) {
        size_t o = (size_t)i * NN_ + (size_t)(m0 + r) * N_ + k0 + tx;
        out[o] = __float2half_rn(t[tx][r]);
    }
}
__global__ void conv_copy(const float* __restrict__ src, __half* __restrict__ dst)
{
    size_t e = ((size_t)blockIdx.x * blockDim.x + threadIdx.x) * 2;
    float2 v = *(const float2*)(src + e);
    *(__half2*)(dst + e) = __floats2half2_rn(v.x, v.y);
}
__global__ void convt_H(const float* __restrict__ H, __half* __restrict__ out)
{
    __shared__ float t[32][33];
    const int n0 = blockIdx.x * 32, d0 = blockIdx.y * 32, z = blockIdx.z;
    const int tx = threadIdx.x & 31, ty = threadIdx.x >> 5;
    const float* Hz = H + (size_t)z * N_ * D_;
    for (int r = ty; r < 32; r += 8)
        t[r][tx] = Hz[(size_t)(n0 + r) * D_ + d0 + tx];
    __syncthreads();
    for (int r = ty; r < 32; r += 8) {
        size_t o = ((size_t)z * D_ + d0 + r) * N_ + n0 + tx;
        out[o] = __float2half_rn(t[tx][r]);
    }
}
__global__ void convt_W(const float* __restrict__ W, int K, int N, __half* __restrict__ out)
{
    __shared__ float t[32][33];
    const int k0 = blockIdx.x * 32, n0 = blockIdx.y * 32;
    const int tx = threadIdx.x & 31, ty = threadIdx.x >> 5;
    for (int r = ty; r < 32; r += 8)
        t[r][tx] = W[(size_t)(k0 + r) * N + n0 + tx];
    __syncthreads();
    for (int r = ty; r < 32; r += 8) {
        size_t o = (size_t)(n0 + r) * K + k0 + tx;
        out[o] = __float2half_rn(t[tx][r]);
    }
}
__global__ void bias_cat(const float* __restrict__ d, const float* __restrict__ s,
                         const float* __restrict__ o, float* __restrict__ out)
{
    int l = blockIdx.x, t = threadIdx.x;
    const float* src = (t < 256) ? d : ((t < 512) ? s : o);
    out[l * 768 + t] = src[l * 256 + (t & 255)];
}
__global__ void conv_plain(const float* __restrict__ src, __half* __restrict__ x)
{
    size_t e = ((size_t)blockIdx.x * blockDim.x + threadIdx.x) * 2;
    size_t row = e >> 7;
    int col = (int)(e & 127);
    float2 v = *(const float2*)(src + e);
    *(__half2*)(x + row * XLD_ + col) = __floats2half2_rn(v.x, v.y);
}
__global__ void transpose_convert_bt(const float* __restrict__ h, __half* __restrict__ x)
{
    size_t gid = (size_t)blockIdx.x * blockDim.x + threadIdx.x;
    int q = (int)(gid & 31);
    int r = (int)(gid >> 5);
    int t = r % T_;
    int bn = r / T_;
    int n = bn % N_;
    int b = bn / N_;
    size_t src = ((size_t)((b * T_ + t) * N_) + n) * D_ + q * 4;
    float4 v = *(const float4*)(h + src);
    size_t o = (size_t)r * XTLD_ + q * 4;
    *(__half2*)(x + o)     = __floats2half2_rn(v.x, v.y);
    *(__half2*)(x + o + 2) = __floats2half2_rn(v.z, v.w);
}

// ---------------- HMMA GEMM infrastructure (k64, swizzled, 3-stage) ----------------
#define TILEB_ 16384                  // 128 rows x 128B
#define STAGEB_ (2 * TILEB_)          // 32768
#define NSTG_ 3
#define SMEM_MMA (NSTG_ * STAGEB_)    // 98304

// ---------------- 4-way support einsum (one launch, all independent) -----------
// warp tile 64m x 32n (2x4 warp grid): 6 ldsm.x4 per 16 MMAs.
__global__ void __launch_bounds__(256, 2)
gemm_support4(const __half* __restrict__ A0, const __half* __restrict__ A1,
              const __half* __restrict__ A2, const __half* __restrict__ A3,
              const __half* __restrict__ Bm, __half* __restrict__ Xb)
{
    extern __shared__ char smem[];
    const uint32_t sbase = smem_u32_(smem);
    const int q   = blockIdx.x >> 4;
    const int m0  = (blockIdx.x & 15) * 128;
    const int z   = blockIdx.y;
    const int tid = threadIdx.x;
    const int wid = tid >> 5, lid = tid & 31;
    const int wm = wid & 1, wn = wid >> 1;     // 2 x 4 warp grid
    const int m_off = wm * 64, n_off = wn * 32;

    const __half* Aq = (q == 0) ? A0 : (q == 1) ? A1 : (q == 2) ? A2 : A3;
    __half* Xs = Xb + 128 * (q + 1);
    const __half* gp[2] = { Aq + (size_t)m0 * N_, Bm + (size_t)z * D_ * N_ };

    auto load_stage = [&](int buf, int k0) {
        uint32_t base = sbase + buf * STAGEB_;
#pragma unroll
        for (int i = 0; i < 8; i++) {
            int idx = i * 256 + tid;
            int tile = idx >> 10;
            int rem = idx & 1023;
            int r = rem >> 3, g = rem & 7;
            uint32_t dst = swadr_(base + tile * TILEB_, r, g);
            const void* src = gp[tile] + (size_t)r * N_ + k0 + g * 8;
            asm volatile("cp.async.cg.shared.global [%0], [%1], 16;" :: "r"(dst), "l"(src));
        }
        asm volatile("cp.async.commit_group;" ::: "memory");
    };

    float acc[4][4][4];
#pragma unroll
    for (int mt = 0; mt < 4; mt++)
#pragma unroll
        for (int nt = 0; nt < 4; nt++)
#pragma unroll
            for (int qq = 0; qq < 4; qq++) acc[mt][nt][qq] = 0.f;

    const int a_row = m_off + (lid & 15);
    const int a_g   = (lid >> 4);
    const int b_row = n_off + ((lid >> 4) << 3) + (lid & 7);
    const int b_g   = ((lid >> 3) & 1);

    const int NT = N_ / 64;
    load_stage(0, 0);
    load_stage(1, 64);
    for (int kt = 0; kt < NT; kt++) {
        if (kt + 1 < NT) asm volatile("cp.async.wait_group 1;" ::: "memory");
        else             asm volatile("cp.async.wait_group 0;" ::: "memory");
        __syncthreads();
        if (kt + 2 < NT) load_stage((kt + 2) % NSTG_, (kt + 2) * 64);

        const uint32_t stg = sbase + (kt % NSTG_) * STAGEB_;
        const uint32_t bA = stg, bB = stg + TILEB_;
#pragma unroll
        for (int k16 = 0; k16 < 4; k16++) {
            const int gb = k16 * 2;
            uint32_t ah[4][4];
#pragma unroll
            for (int mt = 0; mt < 4; mt++)
                ldsm4_(ah[mt], swadr_(bA, a_row + mt * 16, gb + a_g));
#pragma unroll
            for (int pt = 0; pt < 2; pt++) {
                uint32_t bh[4];
                ldsm4_(bh, swadr_(bB, b_row + pt * 16, gb + b_g));
#pragma unroll
                for (int mt = 0; mt < 4; mt++) {
#pragma unroll
                    for (int sub = 0; sub < 2; sub++)
                        mma16816_(acc[mt][pt * 2 + sub], ah[mt], bh[2 * sub], bh[2 * sub + 1]);
                }
            }
        }
    }

    // epilogue: Xcat slice
#pragma unroll
    for (int mt = 0; mt < 4; mt++) {
        const size_t r0 = (size_t)z * N_ + m0 + m_off + mt * 16 + (lid >> 2);
        __half* x0 = Xs + r0 * XLD_;
        __half* x1 = Xs + (r0 + 8) * XLD_;
#pragma unroll
        for (int nt = 0; nt < 4; nt++) {
            const int cc = n_off + nt * 8 + (lid & 3) * 2;
            *(__half2*)(x0 + cc) = __floats2half2_rn(acc[mt][nt][0], acc[mt][nt][1]);
            *(__half2*)(x1 + cc) = __floats2half2_rn(acc[mt][nt][2], acc[mt][nt][3]);
        }
    }
}

// ---------------- rows GEMM: C = act( X·Wt + bias ), warp tile 64m x 32n --------
template <int ACT, bool BIAS, bool HOUT>
__global__ void __launch_bounds__(256, 2)
gemm_rows_hmma(const __half* __restrict__ X, const __half* __restrict__ W,
               const float* __restrict__ bias, void* __restrict__ Cv,
               int K, int lda, int ldb, int ldc)
{
    extern __shared__ char smem[];
    const uint32_t sbase = smem_u32_(smem);
    const int j0  = blockIdx.x * 128;
    const int r0  = blockIdx.y * 128;
    const int tid = threadIdx.x;
    const int wid = tid >> 5, lid = tid & 31;
    const int wm = wid & 1, wn = wid >> 1;
    const int m_off = wm * 64, n_off = wn * 32;

    const __half* gp[2] = { X + (size_t)r0 * lda, W + (size_t)j0 * ldb };

    auto load_stage = [&](int buf, int k0) {
        uint32_t base = sbase + buf * STAGEB_;
#pragma unroll
        for (int i = 0; i < 8; i++) {
            int idx = i * 256 + tid;
            int tile = idx >> 10;
            int rem = idx & 1023;
            int r = rem >> 3, g = rem & 7;
            int ld = (tile == 0) ? lda : ldb;
            uint32_t dst = swadr_(base + tile * TILEB_, r, g);
            const void* src = gp[tile] + (size_t)r * ld + k0 + g * 8;
            asm volatile("cp.async.cg.shared.global [%0], [%1], 16;" :: "r"(dst), "l"(src));
        }
        asm volatile("cp.async.commit_group;" ::: "memory");
    };

    float acc[4][4][4];
#pragma unroll
    for (int mt = 0; mt < 4; mt++)
#pragma unroll
        for (int nt = 0; nt < 4; nt++)
#pragma unroll
            for (int q = 0; q < 4; q++) acc[mt][nt][q] = 0.f;

    const int a_row = m_off + (lid & 15);
    const int a_g   = (lid >> 4);
    const int b_row = n_off + ((lid >> 4) << 3) + (lid & 7);
    const int b_g   = ((lid >> 3) & 1);

    const int NT = K >> 6;
    load_stage(0, 0);
    load_stage(1, 64);
    for (int kt = 0; kt < NT; kt++) {
        if (kt + 1 < NT) asm volatile("cp.async.wait_group 1;" ::: "memory");
        else             asm volatile("cp.async.wait_group 0;" ::: "memory");
        __syncthreads();
        if (kt + 2 < NT) load_stage((kt + 2) % NSTG_, (kt + 2) * 64);

        const uint32_t stg = sbase + (kt % NSTG_) * STAGEB_;
        const uint32_t bA = stg, bB = stg + TILEB_;
#pragma unroll
        for (int k16 = 0; k16 < 4; k16++) {
            const int gb = k16 * 2;
            uint32_t ah[4][4];
#pragma unroll
            for (int mt = 0; mt < 4; mt++)
                ldsm4_(ah[mt], swadr_(bA, a_row + mt * 16, gb + a_g));
#pragma unroll
            for (int pt = 0; pt < 2; pt++) {
                uint32_t bh[4];
                ldsm4_(bh, swadr_(bB, b_row + pt * 16, gb + b_g));
#pragma unroll
                for (int mt = 0; mt < 4; mt++) {
#pragma unroll
                    for (int sub = 0; sub < 2; sub++)
                        mma16816_(acc[mt][pt * 2 + sub], ah[mt], bh[2 * sub], bh[2 * sub + 1]);
                }
            }
        }
    }

    auto ep = [&](float v, float b) -> float {
        if (BIAS) v += b;
        if (ACT == 1) v = softplusf_(v);
        else if (ACT == 2) v = tanhf(v);
        else if (ACT == 3) v = (j0 < 256) ? softplusf_(v) : tanhf(v);
        else if (ACT == 4) v = geluf_(v);
        return v;
    };
#pragma unroll
    for (int mt = 0; mt < 4; mt++) {
        const int r = r0 + m_off + mt * 16 + (lid >> 2);
#pragma unroll
        for (int nt = 0; nt < 4; nt++) {
            const int cc = n_off + nt * 8 + (lid & 3) * 2;
            float b0 = 0.f, b1 = 0.f;
            if (BIAS) { b0 = bias[j0 + cc]; b1 = bias[j0 + cc + 1]; }
            float v0 = ep(acc[mt][nt][0], b0), v1 = ep(acc[mt][nt][1], b1);
            float v2 = ep(acc[mt][nt][2], b0), v3 = ep(acc[mt][nt][3], b1);
            if (HOUT) {
                __half* c0 = (__half*)Cv + (size_t)r * ldc + j0 + cc;
                __half* c1 = (__half*)Cv + (size_t)(r + 8) * ldc + j0 + cc;
                *(__half2*)c0 = __floats2half2_rn(v0, v1);
                *(__half2*)c1 = __floats2half2_rn(v2, v3);
            } else {
                float* c0 = (float*)Cv + (size_t)r * ldc + j0 + cc;
                float* c1 = (float*)Cv + (size_t)(r + 8) * ldc + j0 + cc;
                *(float2*)c0 = make_float2(v0, v1);
                *(float2*)c1 = make_float2(v2, v3);
            }
        }
    }
}

// ---------------- causal depthwise conv (K=4) + SiLU; sig -> Xt cols 0..255 -----
__global__ void conv_silu_kernel(const __half* __restrict__ pr, const float* __restrict__ cw,
                                 const float* __restrict__ cb, __half* __restrict__ x)
{
    int idx = blockIdx.x * blockDim.x + threadIdx.x;
    int c = idx & (INNER_ - 1);
    int bn = idx >> 8;
    float w0 = cw[c * 4 + 0], w1 = cw[c * 4 + 1], w2 = cw[c * 4 + 2], w3 = cw[c * 4 + 3];
    float b = cb[c];
    float s[T_];
    size_t base = (size_t)bn * T_ * 512 + c;
#pragma unroll
    for (int t = 0; t < T_; t++) s[t] = __half2float(pr[base + (size_t)t * 512]);
    size_t ox = (size_t)bn * T_ * XTLD_ + c;
#pragma unroll
    for (int t = 0; t < T_; t++) {
        float a = b + w3 * s[t];
        if (t >= 1) a += w2 * s[t - 1];
        if (t >= 2) a += w1 * s[t - 2];
        if (t >= 3) a += w0 * s[t - 3];
        float v = a * sigmoidf_(a);
        x[ox + (size_t)t * XTLD_] = __float2half_rn(v);
    }
}

// ---------------- selective-scan + gating; reads Xt sig, overwrites with y ------
__global__ void scan_kernel(const __half* __restrict__ dso, const __half* __restrict__ pr,
                            const float* __restrict__ a_log, const float* __restrict__ d_skip,
                            __half* x)
{
    int idx = blockIdx.x * blockDim.x + threadIdx.x;
    int c = idx & (INNER_ - 1);
    int bn = idx >> 8;
    float a = -softplusf_(a_log[c]);
    float dsk = d_skip[c];
    float state = 0.f;
    size_t b768 = (size_t)bn * T_ * 768 + c;
    size_t b512 = (size_t)bn * T_ * 512 + c;
    size_t bx   = (size_t)bn * T_ * XTLD_ + c;
#pragma unroll
    for (int t = 0; t < T_; t++) {
        float xs = __half2float(x  [bx   + (size_t)t * XTLD_]);
        float d  = __half2float(dso[b768 + (size_t)t * 768]);
        float iv = __half2float(dso[b768 + (size_t)t * 768 + 256]);
        float ov = __half2float(dso[b768 + (size_t)t * 768 + 512]);
        float g  = __half2float(pr [b512 + (size_t)t * 512 + INNER_]);
        state = expf(d * a) * state + iv * xs;
        float yy = (ov * state + dsk * xs) * sigmoidf_(g);
        x[bx + (size_t)t * XTLD_] = __float2half_rn(yy);
    }
}

// ---------------- fusion + LayerNorm (sp gelu'd fp16, tp fp16); emits X h slice --
__global__ void fuse_ln_kernel(const float* __restrict__ h_in, const __half* __restrict__ sp,
                               const __half* __restrict__ tp,
                               const float* __restrict__ ln_g, const float* __restrict__ ln_b,
                               float* __restrict__ h_out, __half* __restrict__ xo)
{
    int token = blockIdx.x;
    int d = threadIdx.x;
    int n  = token % N_;
    int bt = token / N_;
    int t  = bt % T_;
    int b  = bt / T_;
    size_t row    = (size_t)token * D_;
    size_t row_tp = ((size_t)(b * N_ + n) * T_ + t) * D_;

    float hv = h_in[row + d];
    float s = __half2float(sp[row + d]);
    float tv = __half2float(tp[row_tp + d]);
    float f = hv + s + tv + s * tv;

    __shared__ float red[8];
    float v = f;
#pragma unroll
    for (int o = 16; o > 0; o >>= 1) v += __shfl_xor_sync(0xffffffffu, v, o);
    if ((d & 31) == 0) red[d >> 5] = v;
    __syncthreads();
    float mu = (red[0] + red[1] + red[2] + red[3]) * (1.f / 128.f);
    float dv = f - mu;
    v = dv * dv;
#pragma unroll
    for (int o = 16; o > 0; o >>= 1) v += __shfl_xor_sync(0xffffffffu, v, o);
    if ((d & 31) == 0) red[4 + (d >> 5)] = v;
    __syncthreads();
    float var = (red[4] + red[5] + red[6] + red[7]) * (1.f / 128.f);
    float out = dv * rsqrtf(var + 1e-5f) * ln_g[d] + ln_b[d];
    h_out[row + d] = out;
    xo[(size_t)token * XLD_ + d] = __float2half_rn(out);
}

// ---------------- host launcher ----------------
extern "C" void kernel_launch(void* const* d_in, const int* in_sizes, int n_in,
                              void* d_out, int out_size)
{
    (void)in_sizes; (void)n_in; (void)out_size;
    const float* inputs   = (const float*)d_in[0];
    const float* supports = (const float*)d_in[1];
    const float* gcn_w    = (const float*)d_in[2];
    const float* gcn_b    = (const float*)d_in[3];
    const float* in_w     = (const float*)d_in[4];
    const float* in_b     = (const float*)d_in[5];
    const float* conv_w   = (const float*)d_in[6];
    const float* conv_b   = (const float*)d_in[7];
    const float* delta_w  = (const float*)d_in[8];
    const float* delta_b  = (const float*)d_in[9];
    const float* si_w     = (const float*)d_in[10];
    const float* si_b     = (const float*)d_in[11];
    const float* so_w     = (const float*)d_in[12];
    const float* so_b     = (const float*)d_in[13];
    const float* a_log    = (const float*)d_in[14];
    const float* d_skip   = (const float*)d_in[15];
    const float* out_w    = (const float*)d_in[16];
    const float* out_b    = (const float*)d_in[17];
    const float* ln_g     = (const float*)d_in[18];
    const float* ln_b     = (const float*)d_in[19];

    float *h2, *bcat;
    __half *sp, *tp, *St, *Sh, *St2, *X, *Xt, *Wt, *Ht0, *pr, *dso;
    cudaGetSymbolAddress((void**)&h2,   g_h2);
    cudaGetSymbolAddress((void**)&bcat, g_bcat);
    cudaGetSymbolAddress((void**)&sp,   g_sp);
    cudaGetSymbolAddress((void**)&tp,   g_tp);
    cudaGetSymbolAddress((void**)&St,   g_St);
    cudaGetSymbolAddress((void**)&Sh,   g_Sh);
    cudaGetSymbolAddress((void**)&St2,  g_St2);
    cudaGetSymbolAddress((void**)&X,    g_X);
    cudaGetSymbolAddress((void**)&Xt,   g_Xt);
    cudaGetSymbolAddress((void**)&Wt,   g_Wt);
    cudaGetSymbolAddress((void**)&Ht0,  g_Ht0);
    cudaGetSymbolAddress((void**)&pr,   g_pr);
    cudaGetSymbolAddress((void**)&dso,  g_dso);

    static cudaStream_t s1 = nullptr;
    static cudaEvent_t evF[2], evJ[2];
    if (s1 == nullptr) {
        cudaStreamCreateWithFlags(&s1, cudaStreamNonBlocking);
        for (int i = 0; i < 2; i++) {
            cudaEventCreateWithFlags(&evF[i], cudaEventDisableTiming);
            cudaEventCreateWithFlags(&evJ[i], cudaEventDisableTiming);
        }
    }

    cudaFuncSetAttribute(gemm_support4, cudaFuncAttributeMaxDynamicSharedMemorySize, SMEM_MMA);
    cudaFuncSetAttribute(gemm_rows_hmma<0,true ,true >, cudaFuncAttributeMaxDynamicSharedMemorySize, SMEM_MMA);
    cudaFuncSetAttribute(gemm_rows_hmma<0,false,true >, cudaFuncAttributeMaxDynamicSharedMemorySize, SMEM_MMA);
    cudaFuncSetAttribute(gemm_rows_hmma<3,true ,true >, cudaFuncAttributeMaxDynamicSharedMemorySize, SMEM_MMA);
    cudaFuncSetAttribute(gemm_rows_hmma<4,true ,true >, cudaFuncAttributeMaxDynamicSharedMemorySize, SMEM_MMA);

    const dim3 blk(256);
    const dim3 gmma4(64, BT_);
    const dim3 gcvH(64, 4, BT_);
    const dim3 gr1(1, ROWS_ / 128);
    const dim3 gr4(4, ROWS_ / 128);
    const dim3 gr6(6, ROWS_ / 128);
    const int ew_blocks = (BN_ * INNER_) / 256;

    // ---- prologue phase 1: temporal prerequisites, then fork layer-0 temporal ----
    for (int l = 0; l < 2; l++) {
        __half* w = Wt + (size_t)l * WSZ_L;
        convt_W<<<dim3(4, 16), blk>>>(in_w   + (size_t)l * 128 * 512, 128, 512, w + WOFF_IN);
        convt_W<<<dim3(8, 8),  blk>>>(delta_w + (size_t)l * 256 * 256, 256, 256, w + WOFF_DL);
        convt_W<<<dim3(8, 8),  blk>>>(si_w    + (size_t)l * 256 * 256, 256, 256, w + WOFF_DL + 65536);
        convt_W<<<dim3(8, 8),  blk>>>(so_w    + (size_t)l * 256 * 256, 256, 256, w + WOFF_DL + 131072);
        convt_W<<<dim3(8, 4),  blk>>>(out_w   + (size_t)l * 256 * 128, 256, 128, w + WOFF_OUT);
    }
    bias_cat<<<2, 768>>>(delta_b, si_b, so_b, bcat);
    cudaEventRecord(evF[0], 0);

    // ---- prologue phase 2: spatial setup (overlaps layer-0 temporal) ----
    for (int l = 0; l < 2; l++)
        convt_W<<<dim3(20, 4), blk>>>(gcn_w + (size_t)l * 640 * 128, 640, 128,
                                      Wt + (size_t)l * WSZ_L + WOFF_GCN);
    convt_S<<<dim3(64, 64, 2), blk>>>(supports, St);
    conv_copy<<<(int)(2 * NN_ / 512), blk>>>(supports, Sh);
    conv_plain<<<(int)(SZ_H / 512), blk>>>(inputs, X);
    gemm_rows_hmma<0,false,true><<<dim3(16, 16), blk, SMEM_MMA>>>(St,       Sh,       nullptr, St2,       2048, 2048, 2048, 2048);
    gemm_rows_hmma<0,false,true><<<dim3(16, 16), blk, SMEM_MMA>>>(St + NN_, Sh + NN_, nullptr, St2 + NN_, 2048, 2048, 2048, 2048);

    for (int l = 0; l < 2; l++) {
        const float* h_in  = (l == 0) ? inputs : h2;
        float*       h_out = (l == 0) ? h2 : (float*)d_out;
        const __half* w = Wt + (size_t)l * WSZ_L;
        const float* gb  = gcn_b  + l * 128;
        const float* ib  = in_b   + l * 512;
        const float* cw  = conv_w + (size_t)l * INNER_ * 4;
        const float* cb  = conv_b + l * INNER_;
        const float* al  = a_log  + l * INNER_;
        const float* dsk = d_skip + l * INNER_;
        const float* ob  = out_b + l * 128;
        const float* lg  = ln_g + l * 128;
        const float* lb  = ln_b + l * 128;

        // ---- fork: temporal branch on s1 ----
        if (l > 0) cudaEventRecord(evF[l], 0);
        cudaStreamWaitEvent(s1, evF[l], 0);
        transpose_convert_bt<<<(ROWS_ * 32) / 256, 256, 0, s1>>>(h_in, Xt);
        gemm_rows_hmma<0,true,true ><<<gr4, blk, SMEM_MMA, s1>>>(Xt, w + WOFF_IN, ib, pr, 128, XTLD_, 128, 512);
        conv_silu_kernel<<<ew_blocks, 256, 0, s1>>>(pr, cw, cb, Xt);
        gemm_rows_hmma<3,true,true ><<<gr6, blk, SMEM_MMA, s1>>>(Xt, w + WOFF_DL, bcat + l * 768, dso, 256, XTLD_, 256, 768);
        scan_kernel<<<ew_blocks, 256, 0, s1>>>(dso, pr, al, dsk, Xt);
        gemm_rows_hmma<0,true,true ><<<gr1, blk, SMEM_MMA, s1>>>(Xt, w + WOFF_OUT, ob, tp, 256, XTLD_, 256, 128);
        cudaEventRecord(evJ[l], s1);

        // ---- spatial branch: convt_H -> 4-way einsum -> gcn GEMM (bias+gelu, fp16 out) ----
        convt_H<<<gcvH, blk>>>(h_in, Ht0);
        gemm_support4<<<gmma4, blk, SMEM_MMA>>>(St, St2, St + NN_, St2 + NN_, Ht0, X);
        gemm_rows_hmma<4,true,true><<<gr1, blk, SMEM_MMA>>>(X, w + WOFF_GCN, gb, sp, 640, XLD_, 640, 128);

        // ---- join + fusion/layernorm ----
        cudaStreamWaitEvent(0, evJ[l], 0);
        fuse_ln_kernel<<<ROWS_, 128>>>(h_in, sp, tp, lg, lb, h_out, X);
    }
}

// round 17
// speedup vs baseline: 1.0538x; 1.0074x over previous
#include <cuda_runtime.h>
#include <cuda_fp16.h>
#include <math.h>
#include <stdint.h>

// ---------------- problem constants ----------------
#define B_    16
#define T_    12
#define N_    2048
#define D_    128
#define INNER_ 256
#define BT_   (B_*T_)          // 192
#define ROWS_ (B_*T_*N_)       // 393216
#define BN_   (B_*N_)          // 32768
#define NN_   ((size_t)N_*N_)
#define XLD_  640              // Xcat row stride (spatial concat)
#define XTLD_ 256              // Xt row stride (temporal)

// ---------------- scratch (device globals) ----------------
#define SZ_H  ((size_t)ROWS_*D_)
#define SZ_PR ((size_t)ROWS_*512)
#define SZ_DSO ((size_t)ROWS_*768)
#define SZ_X  ((size_t)ROWS_*XLD_)
#define SZ_XT ((size_t)ROWS_*XTLD_)
#define SZ_HT ((size_t)BT_*D_*N_)

__device__ __align__(16) float g_h2  [SZ_H];
__device__ __align__(16) float g_bcat[2*768];

__device__ __align__(16) __half g_sp [SZ_H];
__device__ __align__(16) __half g_tp [SZ_H];
__device__ __align__(16) __half g_pr [SZ_PR];
__device__ __align__(16) __half g_dso[SZ_DSO];
__device__ __align__(16) __half g_X  [SZ_X];
__device__ __align__(16) __half g_Xt [SZ_XT];
__device__ __align__(16) __half g_St [2*NN_];
__device__ __align__(16) __half g_Sh [2*NN_];
__device__ __align__(16) __half g_St2[2*NN_];
__device__ __align__(16) __half g_Ht0[SZ_HT];

#define WOFF_GCN 0
#define WOFF_IN  81920
#define WOFF_DL  147456
#define WOFF_OUT 344064
#define WSZ_L    376832
__device__ __align__(16) __half g_Wt[2*WSZ_L];

// ---------------- helpers ----------------
__device__ __forceinline__ float sigmoidf_(float x) { return 1.f / (1.f + expf(-x)); }
__device__ __forceinline__ float softplusf_(float x) {
    return fmaxf(x, 0.f) + log1pf(expf(-fabsf(x)));
}
__device__ __forceinline__ float geluf_(float x) {
    return 0.5f * x * (1.f + erff(x * 0.7071067811865475f));
}
__device__ __forceinline__ uint32_t smem_u32_(const void* p) {
    uint32_t a;
    asm("{ .reg .u64 t; cvta.to.shared.u64 t, %1; cvt.u32.u64 %0, t; }" : "=r"(a) : "l"(p));
    return a;
}
__device__ __forceinline__ void ldsm4_(uint32_t* r, uint32_t a) {
    asm volatile("ldmatrix.sync.aligned.m8n8.x4.shared.b16 {%0,%1,%2,%3}, [%4];"
        : "=r"(r[0]), "=r"(r[1]), "=r"(r[2]), "=r"(r[3]) : "r"(a));
}
__device__ __forceinline__ void mma16816_(float* d, const uint32_t* a, uint32_t b0, uint32_t b1) {
    asm volatile(
        "mma.sync.aligned.m16n8k16.row.col.f32.f16.f16.f32 "
        "{%0,%1,%2,%3}, {%4,%5,%6,%7}, {%8,%9}, {%0,%1,%2,%3};"
        : "+f"(d[0]), "+f"(d[1]), "+f"(d[2]), "+f"(d[3])
        : "r"(a[0]), "r"(a[1]), "r"(a[2]), "r"(a[3]), "r"(b0), "r"(b1));
}
__device__ __forceinline__ uint32_t swadr_(uint32_t base, int row, int g) {
    return base + (uint32_t)(row * 128 + ((g ^ (row & 7)) << 4));
}

// ---------------- merged conversions ----------------
__global__ void convt_W_all(const float* __restrict__ gcn, const float* __restrict__ inw,
                            const float* __restrict__ dlw, const float* __restrict__ siw,
                            const float* __restrict__ sow, const float* __restrict__ outw,
                            __half* __restrict__ Wt)
{
    __shared__ float t[32][33];
    const int l = blockIdx.y;
    const int bx = blockIdx.x;
    const float* W; int K, N; __half* dst; int local;
    if (bx < 80)       { W = gcn + (size_t)l * 640 * 128; K = 640; N = 128; dst = Wt + (size_t)l * WSZ_L + WOFF_GCN; local = bx; }
    else if (bx < 144) { W = inw + (size_t)l * 128 * 512; K = 128; N = 512; dst = Wt + (size_t)l * WSZ_L + WOFF_IN;  local = bx - 80; }
    else if (bx < 208) { W = dlw + (size_t)l * 256 * 256; K = 256; N = 256; dst = Wt + (size_t)l * WSZ_L + WOFF_DL;  local = bx - 144; }
    else if (bx < 272) { W = siw + (size_t)l * 256 * 256; K = 256; N = 256; dst = Wt + (size_t)l * WSZ_L + WOFF_DL + 65536;  local = bx - 208; }
    else if (bx < 336) { W = sow + (size_t)l * 256 * 256; K = 256; N = 256; dst = Wt + (size_t)l * WSZ_L + WOFF_DL + 131072; local = bx - 272; }
    else               { W = outw + (size_t)l * 256 * 128; K = 256; N = 128; dst = Wt + (size_t)l * WSZ_L + WOFF_OUT; local = bx - 336; }
    const int kTiles = K >> 5;
    const int k0 = (local % kTiles) * 32, n0 = (local / kTiles) * 32;
    const int tx = threadIdx.x & 31, ty = threadIdx.x >> 5;
    for (int r = ty; r < 32; r += 8)
        t[r][tx] = W[(size_t)(k0 + r) * N + n0 + tx];
    __syncthreads();
    for (int r = ty; r < 32; r += 8)
        dst[(size_t)(n0 + r) * K + k0 + tx] = __float2half_rn(t[tx][r]);
}
__global__ void convt_S2(const float* __restrict__ S,
                         __half* __restrict__ St, __half* __restrict__ Sh)
{
    __shared__ float t[32][33];
    const int k0 = blockIdx.x * 32, m0 = blockIdx.y * 32, i = blockIdx.z;
    const int tx = threadIdx.x & 31, ty = threadIdx.x >> 5;
    const float* Si = S + (size_t)i * NN_;
    for (int r = ty; r < 32; r += 8) {
        float v = Si[(size_t)(k0 + r) * N_ + m0 + tx];
        t[r][tx] = v;
        Sh[(size_t)i * NN_ + (size_t)(k0 + r) * N_ + m0 + tx] = __float2half_rn(v);
    }
    __syncthreads();
    for (int r = ty; r < 32; r += 8) {
        size_t o = (size_t)i * NN_ + (size_t)(m0 + r) * N_ + k0 + tx;
        St[o] = __float2half_rn(t[tx][r]);
    }
}
__global__ void input_prep(const float* __restrict__ H,
                           __half* __restrict__ X, __half* __restrict__ Ht)
{
    __shared__ float t[32][33];
    const int n0 = blockIdx.x * 32, d0 = blockIdx.y * 32, z = blockIdx.z;
    const int tx = threadIdx.x & 31, ty = threadIdx.x >> 5;
    const float* Hz = H + (size_t)z * N_ * D_;
    for (int r = ty; r < 32; r += 8) {
        float v = Hz[(size_t)(n0 + r) * D_ + d0 + tx];
        t[r][tx] = v;
        X[((size_t)z * N_ + n0 + r) * XLD_ + d0 + tx] = __float2half_rn(v);
    }
    __syncthreads();
    for (int r = ty; r < 32; r += 8) {
        size_t o = ((size_t)z * D_ + d0 + r) * N_ + n0 + tx;
        Ht[o] = __float2half_rn(t[tx][r]);
    }
}
__global__ void convt_H(const float* __restrict__ H, __half* __restrict__ out)
{
    __shared__ float t[32][33];
    const int n0 = blockIdx.x * 32, d0 = blockIdx.y * 32, z = blockIdx.z;
    const int tx = threadIdx.x & 31, ty = threadIdx.x >> 5;
    const float* Hz = H + (size_t)z * N_ * D_;
    for (int r = ty; r < 32; r += 8)
        t[r][tx] = Hz[(size_t)(n0 + r) * D_ + d0 + tx];
    __syncthreads();
    for (int r = ty; r < 32; r += 8) {
        size_t o = ((size_t)z * D_ + d0 + r) * N_ + n0 + tx;
        out[o] = __float2half_rn(t[tx][r]);
    }
}
__global__ void bias_cat(const float* __restrict__ d, const float* __restrict__ s,
                         const float* __restrict__ o, float* __restrict__ out)
{
    int l = blockIdx.x, t = threadIdx.x;
    const float* src = (t < 256) ? d : ((t < 512) ? s : o);
    out[l * 768 + t] = src[l * 256 + (t & 255)];
}
__global__ void transpose_convert_bt(const float* __restrict__ h, __half* __restrict__ x)
{
    size_t gid = (size_t)blockIdx.x * blockDim.x + threadIdx.x;
    int q = (int)(gid & 31);
    int r = (int)(gid >> 5);
    int t = r % T_;
    int bn = r / T_;
    int n = bn % N_;
    int b = bn / N_;
    size_t src = ((size_t)((b * T_ + t) * N_) + n) * D_ + q * 4;
    float4 v = *(const float4*)(h + src);
    size_t o = (size_t)r * XTLD_ + q * 4;
    *(__half2*)(x + o)     = __floats2half2_rn(v.x, v.y);
    *(__half2*)(x + o + 2) = __floats2half2_rn(v.z, v.w);
}

// ---------------- HMMA GEMM infrastructure (k64, swizzled, 3-stage) ----------------
#define TILEB_ 16384
#define STAGEB_ (2 * TILEB_)
#define NSTG_ 3
#define SMEM_MMA (NSTG_ * STAGEB_)    // 98304

// ---------------- 4-way support einsum; warp tile 64m x 32n; staged epilogue ----
__global__ void __launch_bounds__(256, 2)
gemm_support4(const __half* __restrict__ A0, const __half* __restrict__ A1,
              const __half* __restrict__ A2, const __half* __restrict__ A3,
              const __half* __restrict__ Bm, __half* __restrict__ Xb)
{
    extern __shared__ char smem[];
    const uint32_t sbase = smem_u32_(smem);
    const int q   = blockIdx.x >> 4;
    const int m0  = (blockIdx.x & 15) * 128;
    const int z   = blockIdx.y;
    const int tid = threadIdx.x;
    const int wid = tid >> 5, lid = tid & 31;
    const int wm = wid & 1, wn = wid >> 1;
    const int m_off = wm * 64, n_off = wn * 32;

    const __half* Aq = (q == 0) ? A0 : (q == 1) ? A1 : (q == 2) ? A2 : A3;
    __half* Xs = Xb + 128 * (q + 1);
    const __half* gp[2] = { Aq + (size_t)m0 * N_, Bm + (size_t)z * D_ * N_ };

    auto load_stage = [&](int buf, int k0) {
        uint32_t base = sbase + buf * STAGEB_;
#pragma unroll
        for (int i = 0; i < 8; i++) {
            int idx = i * 256 + tid;
            int tile = idx >> 10;
            int rem = idx & 1023;
            int r = rem >> 3, g = rem & 7;
            uint32_t dst = swadr_(base + tile * TILEB_, r, g);
            const void* src = gp[tile] + (size_t)r * N_ + k0 + g * 8;
            asm volatile("cp.async.cg.shared.global [%0], [%1], 16;" :: "r"(dst), "l"(src));
        }
        asm volatile("cp.async.commit_group;" ::: "memory");
    };

    float acc[4][4][4];
#pragma unroll
    for (int mt = 0; mt < 4; mt++)
#pragma unroll
        for (int nt = 0; nt < 4; nt++)
#pragma unroll
            for (int qq = 0; qq < 4; qq++) acc[mt][nt][qq] = 0.f;

    const int a_row = m_off + (lid & 15);
    const int a_g   = (lid >> 4);
    const int b_row = n_off + ((lid >> 4) << 3) + (lid & 7);
    const int b_g   = ((lid >> 3) & 1);

    const int NT = N_ / 64;
    load_stage(0, 0);
    load_stage(1, 64);
    for (int kt = 0; kt < NT; kt++) {
        if (kt + 1 < NT) asm volatile("cp.async.wait_group 1;" ::: "memory");
        else             asm volatile("cp.async.wait_group 0;" ::: "memory");
        __syncthreads();
        if (kt + 2 < NT) load_stage((kt + 2) % NSTG_, (kt + 2) * 64);

        const uint32_t stg = sbase + (kt % NSTG_) * STAGEB_;
        const uint32_t bA = stg, bB = stg + TILEB_;
#pragma unroll
        for (int k16 = 0; k16 < 4; k16++) {
            const int gb = k16 * 2;
            uint32_t ah[4][4];
#pragma unroll
            for (int mt = 0; mt < 4; mt++)
                ldsm4_(ah[mt], swadr_(bA, a_row + mt * 16, gb + a_g));
#pragma unroll
            for (int pt = 0; pt < 2; pt++) {
                uint32_t bh[4];
                ldsm4_(bh, swadr_(bB, b_row + pt * 16, gb + b_g));
#pragma unroll
                for (int mt = 0; mt < 4; mt++) {
#pragma unroll
                    for (int sub = 0; sub < 2; sub++)
                        mma16816_(acc[mt][pt * 2 + sub], ah[mt], bh[2 * sub], bh[2 * sub + 1]);
                }
            }
        }
    }

    // staged epilogue: acc -> smem (272B rows) -> coalesced 128B global stores
    __syncthreads();
    __half* ts = (__half*)smem;      // [128][136]
#pragma unroll
    for (int mt = 0; mt < 4; mt++) {
        const int r = m_off + mt * 16 + (lid >> 2);
#pragma unroll
        for (int nt = 0; nt < 4; nt++) {
            const int cc = n_off + nt * 8 + (lid & 3) * 2;
            *(__half2*)(ts + r * 136 + cc)       = __floats2half2_rn(acc[mt][nt][0], acc[mt][nt][1]);
            *(__half2*)(ts + (r + 8) * 136 + cc) = __floats2half2_rn(acc[mt][nt][2], acc[mt][nt][3]);
        }
    }
    __syncthreads();
    {
        const int row = tid >> 1, hh = tid & 1;
        const uint4* src = (const uint4*)(ts + row * 136 + hh * 64);
        uint4* dst = (uint4*)(Xs + ((size_t)z * N_ + m0 + row) * XLD_ + hh * 64);
#pragma unroll
        for (int i = 0; i < 8; i++) dst[i] = src[i];   // FIXED: full 64-half span
    }
}

// ---------------- rows GEMM: C = act( X·Wt + bias ); optional batch strides ----
template <int ACT, bool BIAS, bool HOUT>
__global__ void __launch_bounds__(256, 2)
gemm_rows_hmma(const __half* __restrict__ X, const __half* __restrict__ W,
               const float* __restrict__ bias, void* __restrict__ Cv,
               int K, int lda, int ldb, int ldc, size_t bstr)
{
    extern __shared__ char smem[];
    const uint32_t sbase = smem_u32_(smem);
    const int j0  = blockIdx.x * 128;
    const int r0  = blockIdx.y * 128;
    const size_t boff = (size_t)blockIdx.z * bstr;
    const int tid = threadIdx.x;
    const int wid = tid >> 5, lid = tid & 31;
    const int wm = wid & 1, wn = wid >> 1;
    const int m_off = wm * 64, n_off = wn * 32;

    const __half* gp[2] = { X + boff + (size_t)r0 * lda, W + boff + (size_t)j0 * ldb };

    auto load_stage = [&](int buf, int k0) {
        uint32_t base = sbase + buf * STAGEB_;
#pragma unroll
        for (int i = 0; i < 8; i++) {
            int idx = i * 256 + tid;
            int tile = idx >> 10;
            int rem = idx & 1023;
            int r = rem >> 3, g = rem & 7;
            int ld = (tile == 0) ? lda : ldb;
            uint32_t dst = swadr_(base + tile * TILEB_, r, g);
            const void* src = gp[tile] + (size_t)r * ld + k0 + g * 8;
            asm volatile("cp.async.cg.shared.global [%0], [%1], 16;" :: "r"(dst), "l"(src));
        }
        asm volatile("cp.async.commit_group;" ::: "memory");
    };

    float acc[4][4][4];
#pragma unroll
    for (int mt = 0; mt < 4; mt++)
#pragma unroll
        for (int nt = 0; nt < 4; nt++)
#pragma unroll
            for (int q = 0; q < 4; q++) acc[mt][nt][q] = 0.f;

    const int a_row = m_off + (lid & 15);
    const int a_g   = (lid >> 4);
    const int b_row = n_off + ((lid >> 4) << 3) + (lid & 7);
    const int b_g   = ((lid >> 3) & 1);

    const int NT = K >> 6;
    load_stage(0, 0);
    load_stage(1, 64);
    for (int kt = 0; kt < NT; kt++) {
        if (kt + 1 < NT) asm volatile("cp.async.wait_group 1;" ::: "memory");
        else             asm volatile("cp.async.wait_group 0;" ::: "memory");
        __syncthreads();
        if (kt + 2 < NT) load_stage((kt + 2) % NSTG_, (kt + 2) * 64);

        const uint32_t stg = sbase + (kt % NSTG_) * STAGEB_;
        const uint32_t bA = stg, bB = stg + TILEB_;
#pragma unroll
        for (int k16 = 0; k16 < 4; k16++) {
            const int gb = k16 * 2;
            uint32_t ah[4][4];
#pragma unroll
            for (int mt = 0; mt < 4; mt++)
                ldsm4_(ah[mt], swadr_(bA, a_row + mt * 16, gb + a_g));
#pragma unroll
            for (int pt = 0; pt < 2; pt++) {
                uint32_t bh[4];
                ldsm4_(bh, swadr_(bB, b_row + pt * 16, gb + b_g));
#pragma unroll
                for (int mt = 0; mt < 4; mt++) {
#pragma unroll
                    for (int sub = 0; sub < 2; sub++)
                        mma16816_(acc[mt][pt * 2 + sub], ah[mt], bh[2 * sub], bh[2 * sub + 1]);
                }
            }
        }
    }

    auto ep = [&](float v, float b) -> float {
        if (BIAS) v += b;
        if (ACT == 1) v = softplusf_(v);
        else if (ACT == 2) v = tanhf(v);
        else if (ACT == 3) v = (j0 < 256) ? softplusf_(v) : tanhf(v);
        else if (ACT == 4) v = geluf_(v);
        return v;
    };
#pragma unroll
    for (int mt = 0; mt < 4; mt++) {
        const int r = r0 + m_off + mt * 16 + (lid >> 2);
#pragma unroll
        for (int nt = 0; nt < 4; nt++) {
            const int cc = n_off + nt * 8 + (lid & 3) * 2;
            float b0 = 0.f, b1 = 0.f;
            if (BIAS) { b0 = bias[j0 + cc]; b1 = bias[j0 + cc + 1]; }
            float v0 = ep(acc[mt][nt][0], b0), v1 = ep(acc[mt][nt][1], b1);
            float v2 = ep(acc[mt][nt][2], b0), v3 = ep(acc[mt][nt][3], b1);
            if (HOUT) {
                __half* c0 = (__half*)Cv + boff + (size_t)r * ldc + j0 + cc;
                __half* c1 = (__half*)Cv + boff + (size_t)(r + 8) * ldc + j0 + cc;
                *(__half2*)c0 = __floats2half2_rn(v0, v1);
                *(__half2*)c1 = __floats2half2_rn(v2, v3);
            } else {
                float* c0 = (float*)Cv + boff + (size_t)r * ldc + j0 + cc;
                float* c1 = (float*)Cv + boff + (size_t)(r + 8) * ldc + j0 + cc;
                *(float2*)c0 = make_float2(v0, v1);
                *(float2*)c1 = make_float2(v2, v3);
            }
        }
    }
}

// ---------------- causal depthwise conv (K=4) + SiLU; sig -> Xt cols 0..255 -----
__global__ void conv_silu_kernel(const __half* __restrict__ pr, const float* __restrict__ cw,
                                 const float* __restrict__ cb, __half* __restrict__ x)
{
    int idx = blockIdx.x * blockDim.x + threadIdx.x;
    int c = idx & (INNER_ - 1);
    int bn = idx >> 8;
    float w0 = cw[c * 4 + 0], w1 = cw[c * 4 + 1], w2 = cw[c * 4 + 2], w3 = cw[c * 4 + 3];
    float b = cb[c];
    float s[T_];
    size_t base = (size_t)bn * T_ * 512 + c;
#pragma unroll
    for (int t = 0; t < T_; t++) s[t] = __half2float(pr[base + (size_t)t * 512]);
    size_t ox = (size_t)bn * T_ * XTLD_ + c;
#pragma unroll
    for (int t = 0; t < T_; t++) {
        float a = b + w3 * s[t];
        if (t >= 1) a += w2 * s[t - 1];
        if (t >= 2) a += w1 * s[t - 2];
        if (t >= 3) a += w0 * s[t - 3];
        float v = a * sigmoidf_(a);
        x[ox + (size_t)t * XTLD_] = __float2half_rn(v);
    }
}

// ---------------- selective-scan + gating; reads Xt sig, overwrites with y ------
__global__ void scan_kernel(const __half* __restrict__ dso, const __half* __restrict__ pr,
                            const float* __restrict__ a_log, const float* __restrict__ d_skip,
                            __half* x)
{
    int idx = blockIdx.x * blockDim.x + threadIdx.x;
    int c = idx & (INNER_ - 1);
    int bn = idx >> 8;
    float a = -softplusf_(a_log[c]);
    float dsk = d_skip[c];
    float state = 0.f;
    size_t b768 = (size_t)bn * T_ * 768 + c;
    size_t b512 = (size_t)bn * T_ * 512 + c;
    size_t bx   = (size_t)bn * T_ * XTLD_ + c;
#pragma unroll
    for (int t = 0; t < T_; t++) {
        float xs = __half2float(x  [bx   + (size_t)t * XTLD_]);
        float d  = __half2float(dso[b768 + (size_t)t * 768]);
        float iv = __half2float(dso[b768 + (size_t)t * 768 + 256]);
        float ov = __half2float(dso[b768 + (size_t)t * 768 + 512]);
        float g  = __half2float(pr [b512 + (size_t)t * 512 + INNER_]);
        state = expf(d * a) * state + iv * xs;
        float yy = (ov * state + dsk * xs) * sigmoidf_(g);
        x[bx + (size_t)t * XTLD_] = __float2half_rn(yy);
    }
}

// ---------------- fusion + LayerNorm; emits X h slice -----------------
__global__ void fuse_ln_kernel(const float* __restrict__ h_in, const __half* __restrict__ sp,
                               const __half* __restrict__ tp,
                               const float* __restrict__ ln_g, const float* __restrict__ ln_b,
                               float* __restrict__ h_out, __half* __restrict__ xo)
{
    int token = blockIdx.x;
    int d = threadIdx.x;
    int n  = token % N_;
    int bt = token / N_;
    int t  = bt % T_;
    int b  = bt / T_;
    size_t row    = (size_t)token * D_;
    size_t row_tp = ((size_t)(b * N_ + n) * T_ + t) * D_;

    float hv = h_in[row + d];
    float s = __half2float(sp[row + d]);
    float tv = __half2float(tp[row_tp + d]);
    float f = hv + s + tv + s * tv;

    __shared__ float red[8];
    float v = f;
#pragma unroll
    for (int o = 16; o > 0; o >>= 1) v += __shfl_xor_sync(0xffffffffu, v, o);
    if ((d & 31) == 0) red[d >> 5] = v;
    __syncthreads();
    float mu = (red[0] + red[1] + red[2] + red[3]) * (1.f / 128.f);
    float dv = f - mu;
    v = dv * dv;
#pragma unroll
    for (int o = 16; o > 0; o >>= 1) v += __shfl_xor_sync(0xffffffffu, v, o);
    if ((d & 31) == 0) red[4 + (d >> 5)] = v;
    __syncthreads();
    float var = (red[4] + red[5] + red[6] + red[7]) * (1.f / 128.f);
    float out = dv * rsqrtf(var + 1e-5f) * ln_g[d] + ln_b[d];
    h_out[row + d] = out;
    xo[(size_t)token * XLD_ + d] = __float2half_rn(out);
}

// ---------------- host launcher ----------------
extern "C" void kernel_launch(void* const* d_in, const int* in_sizes, int n_in,
                              void* d_out, int out_size)
{
    (void)in_sizes; (void)n_in; (void)out_size;
    const float* inputs   = (const float*)d_in[0];
    const float* supports = (const float*)d_in[1];
    const float* gcn_w    = (const float*)d_in[2];
    const float* gcn_b    = (const float*)d_in[3];
    const float* in_w     = (const float*)d_in[4];
    const float* in_b     = (const float*)d_in[5];
    const float* conv_w   = (const float*)d_in[6];
    const float* conv_b   = (const float*)d_in[7];
    const float* delta_w  = (const float*)d_in[8];
    const float* delta_b  = (const float*)d_in[9];
    const float* si_w     = (const float*)d_in[10];
    const float* si_b     = (const float*)d_in[11];
    const float* so_w     = (const float*)d_in[12];
    const float* so_b     = (const float*)d_in[13];
    const float* a_log    = (const float*)d_in[14];
    const float* d_skip   = (const float*)d_in[15];
    const float* out_w    = (const float*)d_in[16];
    const float* out_b    = (const float*)d_in[17];
    const float* ln_g     = (const float*)d_in[18];
    const float* ln_b     = (const float*)d_in[19];

    float *h2, *bcat;
    __half *sp, *tp, *St, *Sh, *St2, *X, *Xt, *Wt, *Ht0, *pr, *dso;
    cudaGetSymbolAddress((void**)&h2,   g_h2);
    cudaGetSymbolAddress((void**)&bcat, g_bcat);
    cudaGetSymbolAddress((void**)&sp,   g_sp);
    cudaGetSymbolAddress((void**)&tp,   g_tp);
    cudaGetSymbolAddress((void**)&St,   g_St);
    cudaGetSymbolAddress((void**)&Sh,   g_Sh);
    cudaGetSymbolAddress((void**)&St2,  g_St2);
    cudaGetSymbolAddress((void**)&X,    g_X);
    cudaGetSymbolAddress((void**)&Xt,   g_Xt);
    cudaGetSymbolAddress((void**)&Wt,   g_Wt);
    cudaGetSymbolAddress((void**)&Ht0,  g_Ht0);
    cudaGetSymbolAddress((void**)&pr,   g_pr);
    cudaGetSymbolAddress((void**)&dso,  g_dso);

    static cudaStream_t s1 = nullptr;
    static cudaEvent_t evF[2], evJ[2];
    if (s1 == nullptr) {
        cudaStreamCreateWithFlags(&s1, cudaStreamNonBlocking);
        for (int i = 0; i < 2; i++) {
            cudaEventCreateWithFlags(&evF[i], cudaEventDisableTiming);
            cudaEventCreateWithFlags(&evJ[i], cudaEventDisableTiming);
        }
    }

    cudaFuncSetAttribute(gemm_support4, cudaFuncAttributeMaxDynamicSharedMemorySize, SMEM_MMA);
    cudaFuncSetAttribute(gemm_rows_hmma<0,true ,true >, cudaFuncAttributeMaxDynamicSharedMemorySize, SMEM_MMA);
    cudaFuncSetAttribute(gemm_rows_hmma<0,false,true >, cudaFuncAttributeMaxDynamicSharedMemorySize, SMEM_MMA);
    cudaFuncSetAttribute(gemm_rows_hmma<3,true ,true >, cudaFuncAttributeMaxDynamicSharedMemorySize, SMEM_MMA);
    cudaFuncSetAttribute(gemm_rows_hmma<4,true ,true >, cudaFuncAttributeMaxDynamicSharedMemorySize, SMEM_MMA);

    const dim3 blk(256);
    const dim3 gmma4(64, BT_);
    const dim3 gcvH(64, 4, BT_);
    const dim3 gr1(1, ROWS_ / 128);
    const dim3 gr4(4, ROWS_ / 128);
    const dim3 gr6(6, ROWS_ / 128);
    const int ew_blocks = (BN_ * INNER_) / 256;

    // ---- prologue (5 launches; einsum l0 becomes launch #5) ----
    convt_W_all<<<dim3(368, 2), blk>>>(gcn_w, in_w, delta_w, si_w, so_w, out_w, Wt);   // [0]
    bias_cat<<<2, 768>>>(delta_b, si_b, so_b, bcat);                                   // [1]
    cudaEventRecord(evF[0], 0);   // temporal prerequisites ready
    convt_S2<<<dim3(64, 64, 2), blk>>>(supports, St, Sh);                              // [2]
    gemm_rows_hmma<0,false,true><<<dim3(16, 16, 2), blk, SMEM_MMA>>>(St, Sh, nullptr, St2,
                                                                     2048, 2048, 2048, 2048, NN_); // [3]
    input_prep<<<gcvH, blk>>>(inputs, X, Ht0);                                         // [4]

    for (int l = 0; l < 2; l++) {
        const float* h_in  = (l == 0) ? inputs : h2;
        float*       h_out = (l == 0) ? h2 : (float*)d_out;
        const __half* w = Wt + (size_t)l * WSZ_L;
        const float* gb  = gcn_b  + l * 128;
        const float* ib  = in_b   + l * 512;
        const float* cw  = conv_w + (size_t)l * INNER_ * 4;
        const float* cb  = conv_b + l * INNER_;
        const float* al  = a_log  + l * INNER_;
        const float* dsk = d_skip + l * INNER_;
        const float* ob  = out_b + l * 128;
        const float* lg  = ln_g + l * 128;
        const float* lb  = ln_b + l * 128;

        // ---- spatial: einsum first (launch [5] for l=0) ----
        gemm_support4<<<gmma4, blk, SMEM_MMA>>>(St, St2, St + NN_, St2 + NN_, Ht0, X);

        // ---- temporal branch on s1 (waits evF[l]) ----
        cudaStreamWaitEvent(s1, evF[l], 0);
        transpose_convert_bt<<<(ROWS_ * 32) / 256, 256, 0, s1>>>(h_in, Xt);
        gemm_rows_hmma<0,true,true ><<<gr4, blk, SMEM_MMA, s1>>>(Xt, w + WOFF_IN, ib, pr, 128, XTLD_, 128, 512, 0);
        conv_silu_kernel<<<ew_blocks, 256, 0, s1>>>(pr, cw, cb, Xt);
        gemm_rows_hmma<3,true,true ><<<gr6, blk, SMEM_MMA, s1>>>(Xt, w + WOFF_DL, bcat + l * 768, dso, 256, XTLD_, 256, 768, 0);
        scan_kernel<<<ew_blocks, 256, 0, s1>>>(dso, pr, al, dsk, Xt);
        gemm_rows_hmma<0,true,true ><<<gr1, blk, SMEM_MMA, s1>>>(Xt, w + WOFF_OUT, ob, tp, 256, XTLD_, 256, 128, 0);
        cudaEventRecord(evJ[l], s1);

        // ---- spatial: gcn GEMM (bias+gelu, fp16 out) ----
        gemm_rows_hmma<4,true,true><<<gr1, blk, SMEM_MMA>>>(X, w + WOFF_GCN, gb, sp, 640, XLD_, 640, 128, 0);

        // ---- join + fusion/layernorm ----
        cudaStreamWaitEvent(0, evJ[l], 0);
        fuse_ln_kernel<<<ROWS_, 128>>>(h_in, sp, tp, lg, lb, h_out, X);
        if (l == 0) {
            cudaEventRecord(evF[1], 0);
            convt_H<<<gcvH, blk>>>(h_out, Ht0);     // layer-1 Ht
        }
    }
}